// round 3
// baseline (speedup 1.0000x reference)
#include <cuda_runtime.h>
#include <math.h>

#define N_NODES 50000
#define D_IN 128
#define MAX_SRC 2048
#define SH_SRC 1024
#define BM_WORDS 1568   // ceil(50000/32)

// persistent device scratch (no allocations)
__device__ int g_deg[N_NODES];
__device__ unsigned g_bitmap[BM_WORDS];
__device__ int g_srcs[MAX_SRC];
__device__ int g_nsrc;
__device__ int g_agent;
__device__ int g_is64;
__device__ unsigned g_count;          // zero-init; self-resets
__device__ volatile unsigned g_sense; // zero-init; toggles, even #barriers -> ends 0

// ---------------------------------------------------------------------------
// sense-reversing grid barrier (all blocks resident: <=1 CTA/SM launched)
// ---------------------------------------------------------------------------
__device__ __forceinline__ void gbar(unsigned* ls) {
    __syncthreads();
    if (threadIdx.x == 0) {
        unsigned target = 1u - *ls;
        *ls = target;
        __threadfence();
        if (atomicAdd(&g_count, 1u) == gridDim.x - 1) {
            g_count = 0;
            __threadfence();
            g_sense = target;
        } else {
            while (g_sense != target) __nanosleep(64);
        }
        __threadfence();
    }
    __syncthreads();
}

// ---------------------------------------------------------------------------
// fused persistent kernel
// ---------------------------------------------------------------------------
__global__ void __launch_bounds__(256, 1) k_fused(
    const float* __restrict__ state,
    const void*  __restrict__ edges,
    const void*  __restrict__ agent_ptr,
    const float* __restrict__ conv_w, const float* __restrict__ conv_b,
    const float* __restrict__ fc1_w,  const float* __restrict__ fc1_b,
    const float* __restrict__ ln1_w,  const float* __restrict__ ln1_b,
    const float* __restrict__ fc2_w,  const float* __restrict__ fc2_b,
    const float* __restrict__ ln2_w,  const float* __restrict__ ln2_b,
    const float* __restrict__ mu_w,   const float* __restrict__ mu_b,
    float* __restrict__ out, long long E)
{
    unsigned ls = 0;
    const int t = threadIdx.x;
    const long long tid  = (long long)blockIdx.x * blockDim.x + t;
    const long long nthr = (long long)gridDim.x * blockDim.x;

    // ---------------- P0: zero scratch; decode dtype + agent -------------
    for (long long i = tid; i < N_NODES; i += nthr) g_deg[i] = 0;
    for (long long i = tid; i < BM_WORDS; i += nthr) g_bitmap[i] = 0;
    if (tid == 0) {
        g_nsrc = 0;
        const int* w = (const int*)edges;
        int is64 = 1;
        #pragma unroll
        for (int j = 0; j < 16; j++)
            if (w[2 * j + 1] != 0) { is64 = 0; break; }
        g_is64 = is64;
        int a = *(const int*)agent_ptr;
        if (a < 0 || a >= N_NODES) a = (int)(*(const float*)agent_ptr);
        g_agent = a;
    }
    gbar(&ls);

    // ---------------- P1: scan dst, collect srcs of edges -> agent -------
    {
        const int agent = g_agent;
        if (g_is64) {
            const long long* src = (const long long*)edges;
            const long long* dst = src + E;
            for (long long i = tid; i < E; i += nthr) {
                if ((int)dst[i] == agent) {
                    int p = atomicAdd(&g_nsrc, 1);
                    if (p < MAX_SRC) g_srcs[p] = (int)src[i];
                }
            }
        } else {
            const int* src = (const int*)edges;
            const int* dst = src + E;
            for (long long i = tid; i < E; i += nthr) {
                if (dst[i] == agent) {
                    int p = atomicAdd(&g_nsrc, 1);
                    if (p < MAX_SRC) g_srcs[p] = src[i];
                }
            }
        }
    }
    gbar(&ls);

    // ---------------- P2: set bitmap bits for the srcs -------------------
    if (blockIdx.x == 0) {
        int n = min(g_nsrc, MAX_SRC);
        for (int m = t; m < n; m += 256) {
            int s = g_srcs[m];
            atomicOr(&g_bitmap[s >> 5], 1u << (s & 31));
        }
    }
    gbar(&ls);

    // ---------------- P3: filtered degree count --------------------------
    {
        if (g_is64) {
            const long long* dst = (const long long*)edges + E;
            for (long long i = tid; i < E; i += nthr) {
                int d = (int)dst[i];
                unsigned wd = g_bitmap[d >> 5];
                if ((wd >> (d & 31)) & 1u) atomicAdd(&g_deg[d], 1);
            }
        } else {
            const int* dst = (const int*)edges + E;
            for (long long i = tid; i < E; i += nthr) {
                int d = dst[i];
                unsigned wd = g_bitmap[d >> 5];
                if ((wd >> (d & 31)) & 1u) atomicAdd(&g_deg[d], 1);
            }
        }
    }
    gbar(&ls);   // 4th barrier: g_sense back to 0 for next replay

    if (blockIdx.x != 0) return;

    // ================= P4: MLP on block 0 ================================
    __shared__ int   ssrc[SH_SRC];
    __shared__ float snorm[SH_SRC];
    __shared__ __align__(16) float agg[D_IN];
    __shared__ __align__(16) float xv[256];
    __shared__ float4 sred[8][32];
    __shared__ float4 cred[4][64];
    __shared__ float rs[64], rq[64];

    const int lane = t & 31, wp = t >> 5;
    const int agent = g_agent;
    const int n = min(g_nsrc, SH_SRC);
    const float dinv_a = rsqrtf((float)(g_nsrc + 1));

    for (int m = t; m < n; m += 256) {
        int s = g_srcs[m];
        ssrc[m]  = s;
        snorm[m] = rsqrtf((float)(g_deg[s] + 1)) * dinv_a;
    }
    __syncthreads();

    // ---- aggregation: warp wp handles sources m = wp, wp+8, ... (float4 rows)
    {
        float4 a = make_float4(0.f, 0.f, 0.f, 0.f);
        for (int m = wp; m < n; m += 8) {
            const float4* row = (const float4*)(state + (size_t)ssrc[m] * D_IN);
            float4 v = __ldg(&row[lane]);
            float nm = snorm[m];
            a.x += nm * v.x; a.y += nm * v.y; a.z += nm * v.z; a.w += nm * v.w;
        }
        sred[wp][lane] = a;
        __syncthreads();
        if (t < 32) {
            float4 s = sred[0][t];
            #pragma unroll
            for (int j = 1; j < 8; j++) {
                float4 b = sred[j][t];
                s.x += b.x; s.y += b.y; s.z += b.z; s.w += b.w;
            }
            const float4* arow = (const float4*)(state + (size_t)agent * D_IN);
            float4 av = __ldg(&arow[t]);
            float c = dinv_a * dinv_a;
            s.x += c * av.x; s.y += c * av.y; s.z += c * av.z; s.w += c * av.w;
            ((float4*)agg)[t] = s;
        }
        __syncthreads();
    }

    const int og = t & 63, sl = t >> 6;

    // ---- conv GEMV (128x256) + relu: thread -> 4 outputs, 4 k-slices of 32
    {
        float4 acc = make_float4(0.f, 0.f, 0.f, 0.f);
        #pragma unroll 4
        for (int kk = 0; kk < 32; kk++) {
            int k = sl * 32 + kk;
            float av = agg[k];
            float4 wv = __ldg((const float4*)(conv_w + k * 256) + og);
            acc.x += av * wv.x; acc.y += av * wv.y; acc.z += av * wv.z; acc.w += av * wv.w;
        }
        cred[sl][og] = acc;
        __syncthreads();
        if (t < 64) {
            float4 r = cred[0][t], b1 = cred[1][t], b2 = cred[2][t], b3 = cred[3][t];
            r.x += b1.x + b2.x + b3.x; r.y += b1.y + b2.y + b3.y;
            r.z += b1.z + b2.z + b3.z; r.w += b1.w + b2.w + b3.w;
            float4 bb = __ldg((const float4*)conv_b + t);
            r.x = fmaxf(r.x + bb.x, 0.f); r.y = fmaxf(r.y + bb.y, 0.f);
            r.z = fmaxf(r.z + bb.z, 0.f); r.w = fmaxf(r.w + bb.w, 0.f);
            ((float4*)xv)[t] = r;
        }
        __syncthreads();
    }

    // ---- fc1 (256x256) + LN + relu, then fc2 identically ---------------
    #pragma unroll 1
    for (int layer = 0; layer < 2; layer++) {
        const float* W  = layer ? fc2_w : fc1_w;
        const float* B  = layer ? fc2_b : fc1_b;
        const float* LW = layer ? ln2_w : ln1_w;
        const float* LB = layer ? ln2_b : ln1_b;

        float4 acc = make_float4(0.f, 0.f, 0.f, 0.f);
        #pragma unroll 4
        for (int kk = 0; kk < 64; kk++) {
            int k = sl * 64 + kk;
            float av = xv[k];
            float4 wv = __ldg((const float4*)(W + k * 256) + og);
            acc.x += av * wv.x; acc.y += av * wv.y; acc.z += av * wv.z; acc.w += av * wv.w;
        }
        cred[sl][og] = acc;
        __syncthreads();

        float4 r;
        if (t < 64) {
            float4 b1 = cred[1][t], b2 = cred[2][t], b3 = cred[3][t];
            r = cred[0][t];
            r.x += b1.x + b2.x + b3.x; r.y += b1.y + b2.y + b3.y;
            r.z += b1.z + b2.z + b3.z; r.w += b1.w + b2.w + b3.w;
            float4 bb = __ldg((const float4*)B + t);
            r.x += bb.x; r.y += bb.y; r.z += bb.z; r.w += bb.w;
            rs[t] = r.x + r.y + r.z + r.w;
            rq[t] = r.x * r.x + r.y * r.y + r.z * r.z + r.w * r.w;
        }
        __syncthreads();
        if (t < 32) {
            float s = rs[t] + rs[t + 32];
            float q = rq[t] + rq[t + 32];
            #pragma unroll
            for (int off = 16; off > 0; off >>= 1) {
                s += __shfl_down_sync(0xffffffffu, s, off);
                q += __shfl_down_sync(0xffffffffu, q, off);
            }
            if (t == 0) { rs[0] = s; rq[0] = q; }
        }
        __syncthreads();
        if (t < 64) {
            float mean = rs[0] * (1.0f / 256.0f);
            float var  = rq[0] * (1.0f / 256.0f) - mean * mean;
            float is   = rsqrtf(var + 1e-5f);
            float4 lw = __ldg((const float4*)LW + t);
            float4 lb = __ldg((const float4*)LB + t);
            r.x = fmaxf((r.x - mean) * is * lw.x + lb.x, 0.f);
            r.y = fmaxf((r.y - mean) * is * lw.y + lb.y, 0.f);
            r.z = fmaxf((r.z - mean) * is * lw.z + lb.z, 0.f);
            r.w = fmaxf((r.w - mean) * is * lw.w + lb.w, 0.f);
            ((float4*)xv)[t] = r;
        }
        __syncthreads();
    }

    // ---- mu head + sigmoid: warp wp -> output wp ------------------------
    {
        float acc = 0.0f;
        #pragma unroll
        for (int k = lane; k < 256; k += 32) acc += xv[k] * __ldg(&mu_w[k * 8 + wp]);
        #pragma unroll
        for (int off = 16; off > 0; off >>= 1)
            acc += __shfl_down_sync(0xffffffffu, acc, off);
        if (lane == 0) {
            float z = acc + mu_b[wp];
            out[wp] = 1.0f / (1.0f + expf(-z));
        }
    }
}

// ---------------------------------------------------------------------------
extern "C" void kernel_launch(void* const* d_in, const int* in_sizes, int n_in,
                              void* d_out, int out_size) {
    const float* state  = (const float*)d_in[0];
    const void*  edges  = d_in[1];
    const void*  agent  = d_in[2];
    const float* conv_w = (const float*)d_in[3];
    const float* conv_b = (const float*)d_in[4];
    const float* fc1_w  = (const float*)d_in[5];
    const float* fc1_b  = (const float*)d_in[6];
    const float* ln1_w  = (const float*)d_in[7];
    const float* ln1_b  = (const float*)d_in[8];
    const float* fc2_w  = (const float*)d_in[9];
    const float* fc2_b  = (const float*)d_in[10];
    const float* ln2_w  = (const float*)d_in[11];
    const float* ln2_b  = (const float*)d_in[12];
    const float* mu_w   = (const float*)d_in[13];
    const float* mu_b   = (const float*)d_in[14];

    long long E = (long long)in_sizes[1] / 2;

    int dev = 0, sms = 0;
    cudaGetDevice(&dev);
    cudaDeviceGetAttribute(&sms, cudaDevAttrMultiProcessorCount, dev);
    if (sms <= 0) sms = 64;

    k_fused<<<sms, 256>>>(state, edges, agent, conv_w, conv_b,
                          fc1_w, fc1_b, ln1_w, ln1_b,
                          fc2_w, fc2_b, ln2_w, ln2_b,
                          mu_w, mu_b, (float*)d_out, E);
}

// round 5
// speedup vs baseline: 1.5232x; 1.5232x over previous
#include <cuda_runtime.h>
#include <math.h>

#define N_NODES 50000
#define D_IN 128
#define MAX_SRC 2048
#define SH_SRC 1024
#define BM_WORDS 1568          // ceil(50000/32)
#define STASH_CAP 11264        // ints (44KB) > ceil(1.6M/148)=10812

// persistent device scratch (no allocations)
__device__ int g_deg[N_NODES];
__device__ unsigned g_bitmap[BM_WORDS];
__device__ int g_srcs[MAX_SRC];
__device__ int g_nsrc;
__device__ int g_agent;
__device__ int g_is64;
__device__ unsigned g_arrive;           // returns to 0 each replay
__device__ volatile unsigned g_epoch;   // monotonic; replay-safe

// ---------------------------------------------------------------------------
// epoch grid barrier (all blocks resident: 1 CTA/SM)
// ---------------------------------------------------------------------------
__device__ __forceinline__ void gbar() {
    __syncthreads();
    if (threadIdx.x == 0) {
        __threadfence();
        unsigned e = g_epoch;
        if (atomicAdd(&g_arrive, 1u) == gridDim.x - 1) {
            g_arrive = 0;
            __threadfence();
            g_epoch = e + 1;
        } else {
            while (g_epoch == e) __nanosleep(32);
        }
        __threadfence();
    }
    __syncthreads();
}

// ---------------------------------------------------------------------------
__global__ void __launch_bounds__(256, 1) k_fused(
    const float* __restrict__ state,
    const void*  __restrict__ edges,
    const void*  __restrict__ agent_ptr,
    const float* __restrict__ conv_w, const float* __restrict__ conv_b,
    const float* __restrict__ fc1_w,  const float* __restrict__ fc1_b,
    const float* __restrict__ ln1_w,  const float* __restrict__ ln1_b,
    const float* __restrict__ fc2_w,  const float* __restrict__ fc2_b,
    const float* __restrict__ ln2_w,  const float* __restrict__ ln2_b,
    const float* __restrict__ mu_w,   const float* __restrict__ mu_b,
    float* __restrict__ out, long long E)
{
    __shared__ __align__(16) unsigned char sbuf[STASH_CAP * 4];
    int* stash = (int*)sbuf;

    const int t = threadIdx.x;
    const long long tid  = (long long)blockIdx.x * blockDim.x + t;
    const long long nthr = (long long)gridDim.x * blockDim.x;

    // ---------------- P0: zero scratch; decode dtype + agent -------------
    for (long long i = tid; i < N_NODES; i += nthr) g_deg[i] = 0;
    for (long long i = tid; i < BM_WORDS; i += nthr) g_bitmap[i] = 0;
    if (tid == 0) {
        g_nsrc = 0;
        const int* w = (const int*)edges;
        int is64 = 1;
        #pragma unroll
        for (int j = 0; j < 16; j++)
            if (w[2 * j + 1] != 0) { is64 = 0; break; }
        g_is64 = is64;
        int a = *(const int*)agent_ptr;
        if (a < 0 || a >= N_NODES) a = (int)(*(const float*)agent_ptr);
        g_agent = a;
    }
    gbar();

    // ---------------- P1: scan dst (stash in smem), collect srcs + bitmap
    const long long chunk = (E + gridDim.x - 1) / gridDim.x;
    const long long start = (long long)blockIdx.x * chunk;
    const long long end   = min(start + chunk, E);
    const int clen = (int)(end - start);
    const bool fits = (chunk <= STASH_CAP);
    {
        const int agent = g_agent;
        if (g_is64) {
            const long long* src = (const long long*)edges;
            const long long* dst = src + E;
            for (int j = t; j < clen; j += 256) {
                int d = (int)dst[start + j];
                if (fits) stash[j] = d;
                if (d == agent) {
                    int p = atomicAdd(&g_nsrc, 1);
                    int s = (int)src[start + j];
                    if (p < MAX_SRC) g_srcs[p] = s;
                    atomicOr(&g_bitmap[s >> 5], 1u << (s & 31));
                }
            }
        } else {
            const int* src = (const int*)edges;
            const int* dst = src + E;
            for (int j = t; j < clen; j += 256) {
                int d = dst[start + j];
                if (fits) stash[j] = d;
                if (d == agent) {
                    int p = atomicAdd(&g_nsrc, 1);
                    int s = src[start + j];
                    if (p < MAX_SRC) g_srcs[p] = s;
                    atomicOr(&g_bitmap[s >> 5], 1u << (s & 31));
                }
            }
        }
    }
    gbar();

    // ---------------- P2: filtered degree histogram (from smem stash) ----
    if (fits) {
        for (int j = t; j < clen; j += 256) {
            int d = stash[j];
            unsigned wd = __ldg(&g_bitmap[d >> 5]);
            if ((wd >> (d & 31)) & 1u) atomicAdd(&g_deg[d], 1);
        }
    } else {
        const long long* dst64 = (const long long*)edges + E;
        const int*       dst32 = (const int*)edges + E;
        for (int j = t; j < clen; j += 256) {
            int d = g_is64 ? (int)dst64[start + j] : dst32[start + j];
            unsigned wd = __ldg(&g_bitmap[d >> 5]);
            if ((wd >> (d & 31)) & 1u) atomicAdd(&g_deg[d], 1);
        }
    }
    gbar();

    if (blockIdx.x != 0) return;

    // ================= MLP on block 0 (smem overlaid on stash) ===========
    float*  agg   = (float*)(sbuf);                 // 128 f   [0,512)
    float*  xv    = (float*)(sbuf + 512);           // 256 f   [512,1536)
    float4* sred  = (float4*)(sbuf + 1536);         // 8*32 f4 [1536,5632)
    float4* cred  = (float4*)(sbuf + 5632);         // 4*64 f4 [5632,9728)
    float*  rs    = (float*)(sbuf + 9728);          // 64 f
    float*  rq    = (float*)(sbuf + 9984);          // 64 f
    int*    ssrc  = (int*)(sbuf + 10240);           // 1024 i  [10240,14336)
    float*  snorm = (float*)(sbuf + 14336);         // 1024 f  [14336,18432)

    const int lane = t & 31, wp = t >> 5;
    const int agent = g_agent;
    const int n = min(g_nsrc, SH_SRC);
    const float dinv_a = rsqrtf((float)(g_nsrc + 1));

    __syncthreads();   // stash -> MLP scratch reuse
    for (int m = t; m < n; m += 256) {
        int s = g_srcs[m];
        ssrc[m]  = s;
        snorm[m] = rsqrtf((float)(g_deg[s] + 1)) * dinv_a;
    }
    __syncthreads();

    // ---- aggregation: warp wp handles sources m = wp, wp+8, ...
    {
        float4 a = make_float4(0.f, 0.f, 0.f, 0.f);
        for (int m = wp; m < n; m += 8) {
            const float4* row = (const float4*)(state + (size_t)ssrc[m] * D_IN);
            float4 v = __ldg(&row[lane]);
            float nm = snorm[m];
            a.x += nm * v.x; a.y += nm * v.y; a.z += nm * v.z; a.w += nm * v.w;
        }
        sred[wp * 32 + lane] = a;
        __syncthreads();
        if (t < 32) {
            float4 s = sred[t];
            #pragma unroll
            for (int j = 1; j < 8; j++) {
                float4 b = sred[j * 32 + t];
                s.x += b.x; s.y += b.y; s.z += b.z; s.w += b.w;
            }
            const float4* arow = (const float4*)(state + (size_t)agent * D_IN);
            float4 av = __ldg(&arow[t]);
            float c = dinv_a * dinv_a;
            s.x += c * av.x; s.y += c * av.y; s.z += c * av.z; s.w += c * av.w;
            ((float4*)agg)[t] = s;
        }
        __syncthreads();
    }

    const int og = t & 63, sl = t >> 6;

    // ---- conv GEMV (128x256) + relu, 16-wide staged loads ----------------
    {
        float4 a0 = make_float4(0.f,0.f,0.f,0.f), a1 = make_float4(0.f,0.f,0.f,0.f);
        const int kb = sl * 32;
        #pragma unroll
        for (int kk = 0; kk < 32; kk += 16) {
            float4 wv[16];
            #pragma unroll
            for (int j = 0; j < 16; j++)
                wv[j] = __ldg((const float4*)(conv_w + (size_t)(kb + kk + j) * 256) + og);
            #pragma unroll
            for (int j = 0; j < 16; j++) {
                float xs = agg[kb + kk + j];
                if (j & 1) { a1.x += xs*wv[j].x; a1.y += xs*wv[j].y; a1.z += xs*wv[j].z; a1.w += xs*wv[j].w; }
                else       { a0.x += xs*wv[j].x; a0.y += xs*wv[j].y; a0.z += xs*wv[j].z; a0.w += xs*wv[j].w; }
            }
        }
        a0.x += a1.x; a0.y += a1.y; a0.z += a1.z; a0.w += a1.w;
        cred[sl * 64 + og] = a0;
        __syncthreads();
        if (t < 64) {
            float4 r = cred[t], b1 = cred[64 + t], b2 = cred[128 + t], b3 = cred[192 + t];
            r.x += b1.x + b2.x + b3.x; r.y += b1.y + b2.y + b3.y;
            r.z += b1.z + b2.z + b3.z; r.w += b1.w + b2.w + b3.w;
            float4 bb = __ldg((const float4*)conv_b + t);
            r.x = fmaxf(r.x + bb.x, 0.f); r.y = fmaxf(r.y + bb.y, 0.f);
            r.z = fmaxf(r.z + bb.z, 0.f); r.w = fmaxf(r.w + bb.w, 0.f);
            ((float4*)xv)[t] = r;
        }
        __syncthreads();
    }

    // ---- fc1 / fc2: 256x256 GEMV + LN + relu, 16-wide staged loads -------
    #pragma unroll 1
    for (int layer = 0; layer < 2; layer++) {
        const float* W  = layer ? fc2_w : fc1_w;
        const float* B  = layer ? fc2_b : fc1_b;
        const float* LW = layer ? ln2_w : ln1_w;
        const float* LB = layer ? ln2_b : ln1_b;

        float4 a0 = make_float4(0.f,0.f,0.f,0.f), a1 = make_float4(0.f,0.f,0.f,0.f);
        const int kb = sl * 64;
        #pragma unroll
        for (int kk = 0; kk < 64; kk += 16) {
            float4 wv[16];
            #pragma unroll
            for (int j = 0; j < 16; j++)
                wv[j] = __ldg((const float4*)(W + (size_t)(kb + kk + j) * 256) + og);
            #pragma unroll
            for (int j = 0; j < 16; j++) {
                float xs = xv[kb + kk + j];
                if (j & 1) { a1.x += xs*wv[j].x; a1.y += xs*wv[j].y; a1.z += xs*wv[j].z; a1.w += xs*wv[j].w; }
                else       { a0.x += xs*wv[j].x; a0.y += xs*wv[j].y; a0.z += xs*wv[j].z; a0.w += xs*wv[j].w; }
            }
        }
        a0.x += a1.x; a0.y += a1.y; a0.z += a1.z; a0.w += a1.w;
        cred[sl * 64 + og] = a0;
        __syncthreads();

        float4 r;
        if (t < 64) {
            float4 b1 = cred[64 + t], b2 = cred[128 + t], b3 = cred[192 + t];
            r = cred[t];
            r.x += b1.x + b2.x + b3.x; r.y += b1.y + b2.y + b3.y;
            r.z += b1.z + b2.z + b3.z; r.w += b1.w + b2.w + b3.w;
            float4 bb = __ldg((const float4*)B + t);
            r.x += bb.x; r.y += bb.y; r.z += bb.z; r.w += bb.w;
            rs[t] = r.x + r.y + r.z + r.w;
            rq[t] = r.x * r.x + r.y * r.y + r.z * r.z + r.w * r.w;
        }
        __syncthreads();
        if (t < 32) {
            float s = rs[t] + rs[t + 32];
            float q = rq[t] + rq[t + 32];
            #pragma unroll
            for (int off = 16; off > 0; off >>= 1) {
                s += __shfl_down_sync(0xffffffffu, s, off);
                q += __shfl_down_sync(0xffffffffu, q, off);
            }
            if (t == 0) { rs[0] = s; rq[0] = q; }
        }
        __syncthreads();
        if (t < 64) {
            float mean = rs[0] * (1.0f / 256.0f);
            float var  = rq[0] * (1.0f / 256.0f) - mean * mean;
            float is   = rsqrtf(var + 1e-5f);
            float4 lw = __ldg((const float4*)LW + t);
            float4 lb = __ldg((const float4*)LB + t);
            r.x = fmaxf((r.x - mean) * is * lw.x + lb.x, 0.f);
            r.y = fmaxf((r.y - mean) * is * lw.y + lb.y, 0.f);
            r.z = fmaxf((r.z - mean) * is * lw.z + lb.z, 0.f);
            r.w = fmaxf((r.w - mean) * is * lw.w + lb.w, 0.f);
            ((float4*)xv)[t] = r;
        }
        __syncthreads();
    }

    // ---- mu head + sigmoid: warp wp -> output wp -------------------------
    {
        float acc = 0.0f;
        #pragma unroll
        for (int k = lane; k < 256; k += 32) acc += xv[k] * __ldg(&mu_w[k * 8 + wp]);
        #pragma unroll
        for (int off = 16; off > 0; off >>= 1)
            acc += __shfl_down_sync(0xffffffffu, acc, off);
        if (lane == 0) {
            float z = acc + mu_b[wp];
            out[wp] = 1.0f / (1.0f + expf(-z));
        }
    }
}

// ---------------------------------------------------------------------------
extern "C" void kernel_launch(void* const* d_in, const int* in_sizes, int n_in,
                              void* d_out, int out_size) {
    const float* state  = (const float*)d_in[0];
    const void*  edges  = d_in[1];
    const void*  agent  = d_in[2];
    const float* conv_w = (const float*)d_in[3];
    const float* conv_b = (const float*)d_in[4];
    const float* fc1_w  = (const float*)d_in[5];
    const float* fc1_b  = (const float*)d_in[6];
    const float* ln1_w  = (const float*)d_in[7];
    const float* ln1_b  = (const float*)d_in[8];
    const float* fc2_w  = (const float*)d_in[9];
    const float* fc2_b  = (const float*)d_in[10];
    const float* ln2_w  = (const float*)d_in[11];
    const float* ln2_b  = (const float*)d_in[12];
    const float* mu_w   = (const float*)d_in[13];
    const float* mu_b   = (const float*)d_in[14];

    long long E = (long long)in_sizes[1] / 2;

    int dev = 0, sms = 0;
    cudaGetDevice(&dev);
    cudaDeviceGetAttribute(&sms, cudaDevAttrMultiProcessorCount, dev);
    if (sms <= 0) sms = 64;

    k_fused<<<sms, 256>>>(state, edges, agent, conv_w, conv_b,
                          fc1_w, fc1_b, ln1_w, ln1_b,
                          fc2_w, fc2_b, ln2_w, ln2_b,
                          mu_w, mu_b, (float*)d_out, E);
}

// round 6
// speedup vs baseline: 1.6550x; 1.0866x over previous
#include <cuda_runtime.h>
#include <math.h>

#define N_NODES 50000
#define D_IN 128
#define MAX_SRC 2048
#define SH_SRC 1024
#define BM_WORDS 1568          // ceil(50000/32)
#define STASH_CAP 22528        // uint16 entries (44KB) > ceil(1.6M/148)=10812

// persistent device scratch (all zero-initialized; kernel leaves it zeroed)
__device__ int g_deg[N_NODES];
__device__ unsigned g_bitmap[BM_WORDS];
__device__ int g_srcs[MAX_SRC];
__device__ int g_nsrc;
__device__ unsigned g_arrive;           // returns to 0 each replay
__device__ volatile unsigned g_epoch;   // monotonic; replay-safe

// ---------------------------------------------------------------------------
// epoch grid barrier (all blocks resident: 1 CTA/SM)
// ---------------------------------------------------------------------------
__device__ __forceinline__ void gbar() {
    __syncthreads();
    if (threadIdx.x == 0) {
        __threadfence();
        unsigned e = g_epoch;
        if (atomicAdd(&g_arrive, 1u) == gridDim.x - 1) {
            g_arrive = 0;
            __threadfence();
            g_epoch = e + 1;
        } else {
            while (g_epoch == e) __nanosleep(20);
        }
        __threadfence();
    }
    __syncthreads();
}

// ---------------------------------------------------------------------------
__global__ void __launch_bounds__(256, 1) k_fused(
    const float* __restrict__ state,
    const void*  __restrict__ edges,
    const void*  __restrict__ agent_ptr,
    const float* __restrict__ conv_w, const float* __restrict__ conv_b,
    const float* __restrict__ fc1_w,  const float* __restrict__ fc1_b,
    const float* __restrict__ ln1_w,  const float* __restrict__ ln1_b,
    const float* __restrict__ fc2_w,  const float* __restrict__ fc2_b,
    const float* __restrict__ ln2_w,  const float* __restrict__ ln2_b,
    const float* __restrict__ mu_w,   const float* __restrict__ mu_b,
    float* __restrict__ out, long long E)
{
    __shared__ __align__(16) unsigned char sbuf[STASH_CAP * 2];
    unsigned short* stash = (unsigned short*)sbuf;

    const int t = threadIdx.x;

    // ---- local decode: edge dtype + agent (same answer in every block) ----
    int is64 = 1;
    {
        const int* w = (const int*)edges;
        #pragma unroll
        for (int j = 0; j < 16; j++)
            if (w[2 * j + 1] != 0) { is64 = 0; break; }
    }
    int agent = *(const int*)agent_ptr;
    if (agent < 0 || agent >= N_NODES) agent = (int)(*(const float*)agent_ptr);

    // ---- P1: scan this block's dst chunk; stash u16; collect srcs+bitmap --
    long long chunk = (E + gridDim.x - 1) / gridDim.x;
    chunk = (chunk + 3) & ~3LL;                       // multiple of 4
    const long long start = (long long)blockIdx.x * chunk;
    const long long end   = min(start + chunk, E);
    const int clen = (int)max(0LL, end - start);
    const bool fits = (chunk <= STASH_CAP);

    if (is64) {
        const long long* src = (const long long*)edges;
        const long long* dst = src + E;
        const bool vec = fits && ((((size_t)(dst + start)) & 15) == 0);
        if (vec) {
            int j = t * 2;
            const int vlim = clen & ~1;
            for (; j + 1 < vlim; j += 512) {
                longlong2 v = *(const longlong2*)(dst + start + j);
                unsigned pack = (unsigned)(unsigned short)v.x |
                                ((unsigned)(unsigned short)v.y << 16);
                *(unsigned*)(stash + j) = pack;
                if ((int)v.x == agent) {
                    int p = atomicAdd(&g_nsrc, 1);
                    if (p < MAX_SRC) {
                        int s = (int)src[start + j];
                        g_srcs[p] = s;
                        atomicOr(&g_bitmap[s >> 5], 1u << (s & 31));
                    }
                }
                if ((int)v.y == agent) {
                    int p = atomicAdd(&g_nsrc, 1);
                    if (p < MAX_SRC) {
                        int s = (int)src[start + j + 1];
                        g_srcs[p] = s;
                        atomicOr(&g_bitmap[s >> 5], 1u << (s & 31));
                    }
                }
            }
            for (int k = vlim + t; k < clen; k += 256) {
                int d = (int)dst[start + k];
                stash[k] = (unsigned short)d;
                if (d == agent) {
                    int p = atomicAdd(&g_nsrc, 1);
                    if (p < MAX_SRC) {
                        int s = (int)src[start + k];
                        g_srcs[p] = s;
                        atomicOr(&g_bitmap[s >> 5], 1u << (s & 31));
                    }
                }
            }
        } else {
            for (int j = t; j < clen; j += 256) {
                int d = (int)dst[start + j];
                if (fits) stash[j] = (unsigned short)d;
                if (d == agent) {
                    int p = atomicAdd(&g_nsrc, 1);
                    if (p < MAX_SRC) {
                        int s = (int)src[start + j];
                        g_srcs[p] = s;
                        atomicOr(&g_bitmap[s >> 5], 1u << (s & 31));
                    }
                }
            }
        }
    } else {
        const int* src = (const int*)edges;
        const int* dst = src + E;
        const bool vec = fits && ((((size_t)(dst + start)) & 15) == 0);
        if (vec) {
            int j = t * 4;
            const int vlim = clen & ~3;
            for (; j + 3 < vlim; j += 1024) {
                int4 v = *(const int4*)(dst + start + j);
                unsigned p0 = (unsigned)(unsigned short)v.x |
                              ((unsigned)(unsigned short)v.y << 16);
                unsigned p1 = (unsigned)(unsigned short)v.z |
                              ((unsigned)(unsigned short)v.w << 16);
                *(unsigned*)(stash + j)     = p0;
                *(unsigned*)(stash + j + 2) = p1;
                int dd[4] = {v.x, v.y, v.z, v.w};
                #pragma unroll
                for (int q = 0; q < 4; q++) {
                    if (dd[q] == agent) {
                        int p = atomicAdd(&g_nsrc, 1);
                        if (p < MAX_SRC) {
                            int s = src[start + j + q];
                            g_srcs[p] = s;
                            atomicOr(&g_bitmap[s >> 5], 1u << (s & 31));
                        }
                    }
                }
            }
            for (int k = vlim + t; k < clen; k += 256) {
                int d = dst[start + k];
                stash[k] = (unsigned short)d;
                if (d == agent) {
                    int p = atomicAdd(&g_nsrc, 1);
                    if (p < MAX_SRC) {
                        int s = src[start + k];
                        g_srcs[p] = s;
                        atomicOr(&g_bitmap[s >> 5], 1u << (s & 31));
                    }
                }
            }
        } else {
            for (int j = t; j < clen; j += 256) {
                int d = dst[start + j];
                if (fits) stash[j] = (unsigned short)d;
                if (d == agent) {
                    int p = atomicAdd(&g_nsrc, 1);
                    if (p < MAX_SRC) {
                        int s = src[start + j];
                        g_srcs[p] = s;
                        atomicOr(&g_bitmap[s >> 5], 1u << (s & 31));
                    }
                }
            }
        }
    }
    gbar();

    // ---- P2: filtered degree histogram ------------------------------------
    if (fits) {
        for (int j = t; j < clen; j += 256) {
            int d = stash[j];
            unsigned wd = __ldg(&g_bitmap[d >> 5]);
            if ((wd >> (d & 31)) & 1u) atomicAdd(&g_deg[d], 1);
        }
    } else {
        const long long* dst64 = (const long long*)edges + E;
        const int*       dst32 = (const int*)edges + E;
        for (int j = t; j < clen; j += 256) {
            int d = is64 ? (int)dst64[start + j] : dst32[start + j];
            unsigned wd = __ldg(&g_bitmap[d >> 5]);
            if ((wd >> (d & 31)) & 1u) atomicAdd(&g_deg[d], 1);
        }
    }
    gbar();

    if (blockIdx.x != 0) return;

    // ================= MLP on block 0 (smem overlaid on stash) =============
    float*  agg   = (float*)(sbuf);                 // 128 f   [0,512)
    float*  xv    = (float*)(sbuf + 512);           // 256 f   [512,1536)
    float4* sred  = (float4*)(sbuf + 1536);         // 8*32 f4 [1536,5632)
    float4* cred  = (float4*)(sbuf + 5632);         // 4*64 f4 [5632,9728)
    float*  rs    = (float*)(sbuf + 9728);          // 64 f
    float*  rq    = (float*)(sbuf + 9984);          // 64 f
    int*    ssrc  = (int*)(sbuf + 10240);           // 1024 i  [10240,14336)
    float*  snorm = (float*)(sbuf + 14336);         // 1024 f  [14336,18432)

    const int lane = t & 31, wp = t >> 5;
    const int n  = min(g_nsrc, SH_SRC);
    const int nc = min(g_nsrc, MAX_SRC);            // for cleanup
    const float dinv_a = rsqrtf((float)(g_nsrc + 1));

    __syncthreads();   // stash -> MLP scratch reuse
    for (int m = t; m < n; m += 256) {
        int s = g_srcs[m];
        ssrc[m]  = s;
        snorm[m] = rsqrtf((float)(g_deg[s] + 1)) * dinv_a;
    }
    __syncthreads();

    // ---- aggregation: warp wp handles sources m = wp, wp+8, ...
    {
        float4 a = make_float4(0.f, 0.f, 0.f, 0.f);
        for (int m = wp; m < n; m += 8) {
            const float4* row = (const float4*)(state + (size_t)ssrc[m] * D_IN);
            float4 v = __ldg(&row[lane]);
            float nm = snorm[m];
            a.x += nm * v.x; a.y += nm * v.y; a.z += nm * v.z; a.w += nm * v.w;
        }
        sred[wp * 32 + lane] = a;
        __syncthreads();
        if (t < 32) {
            float4 s = sred[t];
            #pragma unroll
            for (int j = 1; j < 8; j++) {
                float4 b = sred[j * 32 + t];
                s.x += b.x; s.y += b.y; s.z += b.z; s.w += b.w;
            }
            const float4* arow = (const float4*)(state + (size_t)agent * D_IN);
            float4 av = __ldg(&arow[t]);
            float c = dinv_a * dinv_a;
            s.x += c * av.x; s.y += c * av.y; s.z += c * av.z; s.w += c * av.w;
            ((float4*)agg)[t] = s;
        }
        __syncthreads();
    }

    const int og = t & 63, sl = t >> 6;

    // ---- conv GEMV (128x256) + relu, 8-wide staged loads -------------------
    {
        float4 a0 = make_float4(0.f,0.f,0.f,0.f), a1 = make_float4(0.f,0.f,0.f,0.f);
        const int kb = sl * 32;
        #pragma unroll
        for (int kk = 0; kk < 32; kk += 8) {
            float4 wv[8];
            #pragma unroll
            for (int j = 0; j < 8; j++)
                wv[j] = __ldg((const float4*)(conv_w + (size_t)(kb + kk + j) * 256) + og);
            #pragma unroll
            for (int j = 0; j < 8; j++) {
                float xs = agg[kb + kk + j];
                if (j & 1) { a1.x += xs*wv[j].x; a1.y += xs*wv[j].y; a1.z += xs*wv[j].z; a1.w += xs*wv[j].w; }
                else       { a0.x += xs*wv[j].x; a0.y += xs*wv[j].y; a0.z += xs*wv[j].z; a0.w += xs*wv[j].w; }
            }
        }
        a0.x += a1.x; a0.y += a1.y; a0.z += a1.z; a0.w += a1.w;
        cred[sl * 64 + og] = a0;
        __syncthreads();
        if (t < 64) {
            float4 r = cred[t], b1 = cred[64 + t], b2 = cred[128 + t], b3 = cred[192 + t];
            r.x += b1.x + b2.x + b3.x; r.y += b1.y + b2.y + b3.y;
            r.z += b1.z + b2.z + b3.z; r.w += b1.w + b2.w + b3.w;
            float4 bb = __ldg((const float4*)conv_b + t);
            r.x = fmaxf(r.x + bb.x, 0.f); r.y = fmaxf(r.y + bb.y, 0.f);
            r.z = fmaxf(r.z + bb.z, 0.f); r.w = fmaxf(r.w + bb.w, 0.f);
            ((float4*)xv)[t] = r;
        }
        __syncthreads();
    }

    // ---- fc1 / fc2: 256x256 GEMV + LN + relu, 8-wide staged loads ----------
    #pragma unroll 1
    for (int layer = 0; layer < 2; layer++) {
        const float* W  = layer ? fc2_w : fc1_w;
        const float* B  = layer ? fc2_b : fc1_b;
        const float* LW = layer ? ln2_w : ln1_w;
        const float* LB = layer ? ln2_b : ln1_b;

        float4 a0 = make_float4(0.f,0.f,0.f,0.f), a1 = make_float4(0.f,0.f,0.f,0.f);
        const int kb = sl * 64;
        #pragma unroll
        for (int kk = 0; kk < 64; kk += 8) {
            float4 wv[8];
            #pragma unroll
            for (int j = 0; j < 8; j++)
                wv[j] = __ldg((const float4*)(W + (size_t)(kb + kk + j) * 256) + og);
            #pragma unroll
            for (int j = 0; j < 8; j++) {
                float xs = xv[kb + kk + j];
                if (j & 1) { a1.x += xs*wv[j].x; a1.y += xs*wv[j].y; a1.z += xs*wv[j].z; a1.w += xs*wv[j].w; }
                else       { a0.x += xs*wv[j].x; a0.y += xs*wv[j].y; a0.z += xs*wv[j].z; a0.w += xs*wv[j].w; }
            }
        }
        a0.x += a1.x; a0.y += a1.y; a0.z += a1.z; a0.w += a1.w;
        cred[sl * 64 + og] = a0;
        __syncthreads();

        float4 r;
        if (t < 64) {
            float4 b1 = cred[64 + t], b2 = cred[128 + t], b3 = cred[192 + t];
            r = cred[t];
            r.x += b1.x + b2.x + b3.x; r.y += b1.y + b2.y + b3.y;
            r.z += b1.z + b2.z + b3.z; r.w += b1.w + b2.w + b3.w;
            float4 bb = __ldg((const float4*)B + t);
            r.x += bb.x; r.y += bb.y; r.z += bb.z; r.w += bb.w;
            rs[t] = r.x + r.y + r.z + r.w;
            rq[t] = r.x * r.x + r.y * r.y + r.z * r.z + r.w * r.w;
        }
        __syncthreads();
        if (t < 32) {
            float s = rs[t] + rs[t + 32];
            float q = rq[t] + rq[t + 32];
            #pragma unroll
            for (int off = 16; off > 0; off >>= 1) {
                s += __shfl_down_sync(0xffffffffu, s, off);
                q += __shfl_down_sync(0xffffffffu, q, off);
            }
            if (t == 0) { rs[0] = s; rq[0] = q; }
        }
        __syncthreads();
        if (t < 64) {
            float mean = rs[0] * (1.0f / 256.0f);
            float var  = rq[0] * (1.0f / 256.0f) - mean * mean;
            float is   = rsqrtf(var + 1e-5f);
            float4 lw = __ldg((const float4*)LW + t);
            float4 lb = __ldg((const float4*)LB + t);
            r.x = fmaxf((r.x - mean) * is * lw.x + lb.x, 0.f);
            r.y = fmaxf((r.y - mean) * is * lw.y + lb.y, 0.f);
            r.z = fmaxf((r.z - mean) * is * lw.z + lb.z, 0.f);
            r.w = fmaxf((r.w - mean) * is * lw.w + lb.w, 0.f);
            ((float4*)xv)[t] = r;
        }
        __syncthreads();
    }

    // ---- mu head + sigmoid: warp wp -> output wp ---------------------------
    {
        float acc = 0.0f;
        #pragma unroll
        for (int k = lane; k < 256; k += 32) acc += xv[k] * __ldg(&mu_w[k * 8 + wp]);
        #pragma unroll
        for (int off = 16; off > 0; off >>= 1)
            acc += __shfl_down_sync(0xffffffffu, acc, off);
        if (lane == 0) {
            float z = acc + mu_b[wp];
            out[wp] = 1.0f / (1.0f + expf(-z));
        }
    }
    __syncthreads();

    // ---- cleanup: reset only touched global state (replay-clean) ----------
    for (int m = t; m < nc; m += 256) {
        int s = g_srcs[m];
        g_bitmap[s >> 5] = 0;
        g_deg[s] = 0;
    }
    if (t == 0) {
        g_deg[agent] = 0;
        g_nsrc = 0;
    }
}

// ---------------------------------------------------------------------------
extern "C" void kernel_launch(void* const* d_in, const int* in_sizes, int n_in,
                              void* d_out, int out_size) {
    const float* state  = (const float*)d_in[0];
    const void*  edges  = d_in[1];
    const void*  agent  = d_in[2];
    const float* conv_w = (const float*)d_in[3];
    const float* conv_b = (const float*)d_in[4];
    const float* fc1_w  = (const float*)d_in[5];
    const float* fc1_b  = (const float*)d_in[6];
    const float* ln1_w  = (const float*)d_in[7];
    const float* ln1_b  = (const float*)d_in[8];
    const float* fc2_w  = (const float*)d_in[9];
    const float* fc2_b  = (const float*)d_in[10];
    const float* ln2_w  = (const float*)d_in[11];
    const float* ln2_b  = (const float*)d_in[12];
    const float* mu_w   = (const float*)d_in[13];
    const float* mu_b   = (const float*)d_in[14];

    long long E = (long long)in_sizes[1] / 2;

    int dev = 0, sms = 0;
    cudaGetDevice(&dev);
    cudaDeviceGetAttribute(&sms, cudaDevAttrMultiProcessorCount, dev);
    if (sms <= 0) sms = 64;

    k_fused<<<sms, 256>>>(state, edges, agent, conv_w, conv_b,
                          fc1_w, fc1_b, ln1_w, ln1_b,
                          fc2_w, fc2_b, ln2_w, ln2_b,
                          mu_w, mu_b, (float*)d_out, E);
}